// round 7
// baseline (speedup 1.0000x reference)
#include <cuda_runtime.h>
#include <cuda_bf16.h>
#include <cstdint>
#include <math.h>

#define N_PTS 600000
#define N_VOX 200000
typedef unsigned long long u64;
typedef unsigned int u32;

// ===================== PTX helpers (family-agnostic, sm_100-safe) =====================
__device__ __forceinline__ u32 smem_to_u32(const void* p) {
    u32 a;
    asm("{ .reg .u64 tmp; cvta.to.shared.u64 tmp, %1; cvt.u32.u64 %0, tmp; }" : "=r"(a) : "l"(p));
    return a;
}
__device__ __forceinline__ void ldmx4(u32* r, u32 addr) {
    asm volatile("ldmatrix.sync.aligned.m8n8.x4.shared.b16 {%0,%1,%2,%3}, [%4];"
        : "=r"(r[0]), "=r"(r[1]), "=r"(r[2]), "=r"(r[3]) : "r"(addr));
}
__device__ __forceinline__ void mma16816(float* d, const u32* a, u32 b0, u32 b1) {
    asm volatile("mma.sync.aligned.m16n8k16.row.col.f32.bf16.bf16.f32 "
        "{%0,%1,%2,%3}, {%4,%5,%6,%7}, {%8,%9}, {%0,%1,%2,%3};"
        : "+f"(d[0]), "+f"(d[1]), "+f"(d[2]), "+f"(d[3])
        : "r"(a[0]), "r"(a[1]), "r"(a[2]), "r"(a[3]), "r"(b0), "r"(b1));
}
__device__ __forceinline__ void cpasync16(u32 dst, const void* src) {
    asm volatile("cp.async.cg.shared.global [%0], [%1], 16;" :: "r"(dst), "l"(src));
}
#define CP_COMMIT() asm volatile("cp.async.commit_group;" ::: "memory")
#define CP_WAIT0()  asm volatile("cp.async.wait_group 0;" ::: "memory")
// packed f32x2 helpers for the FFMA GEMM (layer 1)
__device__ __forceinline__ u64 dup2(float x) { u64 r; asm("mov.b64 %0, {%1, %1};" : "=l"(r) : "f"(x)); return r; }
__device__ __forceinline__ void fma2(u64& d, u64 a, u64 b) { asm("fma.rn.f32x2 %0, %1, %2, %0;" : "+l"(d) : "l"(a), "l"(b)); }
__device__ __forceinline__ void unpack2(float& lo, float& hi, u64 v) { asm("mov.b64 {%0, %1}, %2;" : "=f"(lo), "=f"(hi) : "l"(v)); }

// ===================== static device scratch =====================
static __device__ float  g_h1[(size_t)N_PTS * 64];
static __device__ float  g_h2[(size_t)N_PTS * 128];
static __device__ float  g_h3[(size_t)N_PTS * 256];
static __device__ float  g_pool[(size_t)N_VOX * 256];
static __device__ double g_sum[4][256];
static __device__ double g_sqs[4][256];
static __device__ float  g_scale[4][256];
static __device__ float  g_shift[4][256];
static __device__ __align__(16) __nv_bfloat16 g_w2h[8192],  g_w2l[8192];    // [n=128][k=64]
static __device__ __align__(16) __nv_bfloat16 g_w3h[32768], g_w3l[32768];   // [n=256][k=128]
static __device__ __align__(16) __nv_bfloat16 g_w4h[65536], g_w4l[65536];   // [n=256][k=256]
static __device__ int g_cnt[N_VOX];
static __device__ int g_start[N_VOX + 1];
static __device__ int g_bsum[512];
static __device__ int g_perm[N_PTS];
static __device__ int g_svox[N_PTS];

// ===================== small utility kernels =====================
__global__ void k_zero_stats() {
    int t = threadIdx.x;
    for (int s = 0; s < 4; s++) { g_sum[s][t] = 0.0; g_sqs[s][t] = 0.0; }
}
__global__ void k_zero_cnt() {
    int i = blockIdx.x * blockDim.x + threadIdx.x;
    if (i < N_VOX) g_cnt[i] = 0;
}
// Pool init: NaN sentinel. Boundary atomics absorb it; k_final maps leftovers to 0.
__global__ void k_fill_pool() {
    size_t i = (size_t)blockIdx.x * blockDim.x + threadIdx.x;
    size_t stride = (size_t)gridDim.x * blockDim.x;
    size_t n4 = (size_t)N_VOX * 256 / 4;
    uint4* p = reinterpret_cast<uint4*>(g_pool);
    uint4 v = make_uint4(0xFFFFFFFFu, 0xFFFFFFFFu, 0xFFFFFFFFu, 0xFFFFFFFFu);
    for (; i < n4; i += stride) p[i] = v;
}
__global__ void k_stats_in(const float* __restrict__ x) {
    int t = threadIdx.x;
    int col = t & 15;
    float s = 0.f, q = 0.f;
    size_t i = (size_t)blockIdx.x * blockDim.x + t;
    size_t stride = (size_t)gridDim.x * blockDim.x;
    const size_t total = (size_t)N_PTS * 16;
    for (; i < total; i += stride) { float v = x[i]; s += v; q += v * v; }
    __shared__ float ss[16][16], qq[16][16];
    ss[t >> 4][col] = s; qq[t >> 4][col] = q;
    __syncthreads();
    if (t < 16) {
        float S = 0.f, Q = 0.f;
        #pragma unroll
        for (int r = 0; r < 16; r++) { S += ss[r][t]; Q += qq[r][t]; }
        atomicAdd(&g_sum[0][t], (double)S);
        atomicAdd(&g_sqs[0][t], (double)Q);
    }
}
__global__ void k_prep(const float* __restrict__ g, const float* __restrict__ b, int slot, int C) {
    int t = blockIdx.x * blockDim.x + threadIdx.x;
    if (t >= C) return;
    double mean = g_sum[slot][t] / (double)N_PTS;
    double var  = g_sqs[slot][t] / (double)N_PTS - mean * mean;
    float inv = (float)(1.0 / sqrt(var + 1e-5));
    float sc = g[t] * inv;
    g_scale[slot][t] = sc;
    g_shift[slot][t] = b[t] - (float)mean * sc;
}

// Pre-transpose + bf16 hi/lo split of W2/W3/W4 into [n][k] row-major images.
__global__ void k_wprep(const float* __restrict__ w2, const float* __restrict__ w3,
                        const float* __restrict__ w4) {
    int i = blockIdx.x * 256 + threadIdx.x;
    if (i < 8192) {                                  // layer 2: K=64, N=128
        int n = i >> 6, k = i & 63;
        float w = w2[k * 128 + n];
        __nv_bfloat16 h = __float2bfloat16(w);
        g_w2h[i] = h; g_w2l[i] = __float2bfloat16(w - __bfloat162float(h));
    } else if (i < 8192 + 32768) {                   // layer 3: K=128, N=256
        int j = i - 8192;
        int n = j >> 7, k = j & 127;
        float w = w3[k * 256 + n];
        __nv_bfloat16 h = __float2bfloat16(w);
        g_w3h[j] = h; g_w3l[j] = __float2bfloat16(w - __bfloat162float(h));
    } else if (i < 8192 + 32768 + 65536) {           // layer 4: K=256, N=256
        int j = i - 40960;
        int n = j >> 8, k = j & 255;
        float w = w4[k * 256 + n];
        __nv_bfloat16 h = __float2bfloat16(w);
        g_w4h[j] = h; g_w4l[j] = __float2bfloat16(w - __bfloat162float(h));
    }
}

// ===================== counting sort by voxel =====================
__global__ void k_hist(const int* __restrict__ uinv) {
    int i = blockIdx.x * blockDim.x + threadIdx.x;
    if (i < N_PTS) atomicAdd(&g_cnt[uinv[i]], 1);
}
#define SCB 512
__global__ void k_scan1() {
    int t = threadIdx.x, b = blockIdx.x;
    int i = b * SCB + t;
    int x = (i < N_VOX) ? g_cnt[i] : 0;
    __shared__ int sc[SCB];
    sc[t] = x; __syncthreads();
    for (int ofs = 1; ofs < SCB; ofs <<= 1) {
        int y = (t >= ofs) ? sc[t - ofs] : 0;
        __syncthreads();
        sc[t] += y;
        __syncthreads();
    }
    if (i < N_VOX) g_start[i] = sc[t] - x;
    if (t == SCB - 1) g_bsum[b] = sc[t];
}
__global__ void k_scan2(int nblk) {
    int t = threadIdx.x;
    int x = (t < nblk) ? g_bsum[t] : 0;
    __shared__ int sc[SCB];
    sc[t] = x; __syncthreads();
    for (int ofs = 1; ofs < SCB; ofs <<= 1) {
        int y = (t >= ofs) ? sc[t - ofs] : 0;
        __syncthreads();
        sc[t] += y;
        __syncthreads();
    }
    if (t < nblk) g_bsum[t] = sc[t] - x;
}
__global__ void k_scan3() {
    int t = threadIdx.x, b = blockIdx.x;
    int i = b * SCB + t;
    if (i < N_VOX) g_start[i] += g_bsum[b];
    if (i == 0) g_start[N_VOX] = N_PTS;
}
__global__ void k_scatter(const int* __restrict__ uinv) {
    int i = blockIdx.x * blockDim.x + threadIdx.x;
    if (i < N_PTS) {
        int v = uinv[i];
        int old = atomicAdd(&g_cnt[v], -1);
        int pos = g_start[v] + old - 1;
        g_perm[pos] = i;
        g_svox[pos] = v;
    }
}

// Sign-aware float atomic max (RED at L2; NaN sentinel absorbed by both orderings).
__device__ __forceinline__ void atomicMaxF(float* p, float v) {
    unsigned b = __float_as_uint(v);
    if ((int)b >= 0)           atomicMax((int*)p, (int)b);
    else if (b == 0x80000000u) atomicMax((int*)p, 0);
    else                       atomicMin((unsigned*)p, b);
}

// ===================== FFMA GEMM (layer 1 only, stats epilogue) =====================
template<int K, int TN, bool RELU_IN>
__global__ void __launch_bounds__(256)
k_gemm(const float* __restrict__ A, const float* __restrict__ W,
       const float* __restrict__ bias, int NOUT, int aslot, int sslot,
       float* __restrict__ Hout)
{
    constexpr int TM = 128, KT = 16;
    constexpr int MN = TN / 16;
    constexpr int S  = K / KT;
    constexpr int NB4 = (KT * TN) / (4 * 256);
    constexpr int C4  = TN / 4;

    __shared__ union SmemU {
        struct { float As[2][KT][TM]; float Bs[2][KT][TN]; } mm;
        struct { float r1[16][TN]; float r2[16][TN]; } red;
    } sm;
    __shared__ float s_sc[K], s_sh[K];

    const int t  = threadIdx.x;
    const int tx = t & 15, ty = t >> 4;
    const int bn0 = blockIdx.x * TN;
    const long bm0 = (long)blockIdx.y * TM;

    for (int i = t; i < K; i += 256) { s_sc[i] = g_scale[aslot][i]; s_sh[i] = g_shift[aslot][i]; }

    const int  ar = t & 127;
    const int  ah = t >> 7;
    const long gm = bm0 + ar;
    const bool mval = gm < N_PTS;
    const float* aptr = A + (size_t)(mval ? gm : 0) * K + ah * 8;

    u64 c2[4][MN];
    #pragma unroll
    for (int i = 0; i < 4; i++)
        #pragma unroll
        for (int j = 0; j < MN; j++) c2[i][j] = 0ull;

    float4 ra0, ra1, rb[NB4];
    ra0 = make_float4(0.f, 0.f, 0.f, 0.f); ra1 = ra0;
    if (mval) { ra0 = *(const float4*)(aptr); ra1 = *(const float4*)(aptr + 4); }
    #pragma unroll
    for (int i = 0; i < NB4; i++) {
        int id = t + i * 256;
        int kk = id / C4, c4 = id % C4;
        rb[i] = *(const float4*)(W + (size_t)kk * NOUT + bn0 + c4 * 4);
    }
    __syncthreads();
    {
        float v[8] = {ra0.x, ra0.y, ra0.z, ra0.w, ra1.x, ra1.y, ra1.z, ra1.w};
        #pragma unroll
        for (int j = 0; j < 8; j++) {
            int k = ah * 8 + j;
            float f = fmaf(v[j], s_sc[k], s_sh[k]);
            if (RELU_IN) f = fmaxf(f, 0.f);
            sm.mm.As[0][ah * 8 + j][ar] = mval ? f : 0.f;
        }
        #pragma unroll
        for (int i = 0; i < NB4; i++) {
            int id = t + i * 256;
            int kk = id / C4, c4 = id % C4;
            *(float4*)&sm.mm.Bs[0][kk][c4 * 4] = rb[i];
        }
    }
    __syncthreads();

    for (int s = 0; s < S; s++) {
        const int buf = s & 1;
        if (s + 1 < S) {
            const float* ap = aptr + (s + 1) * KT;
            ra0 = make_float4(0.f, 0.f, 0.f, 0.f); ra1 = ra0;
            if (mval) { ra0 = *(const float4*)ap; ra1 = *(const float4*)(ap + 4); }
            #pragma unroll
            for (int i = 0; i < NB4; i++) {
                int id = t + i * 256;
                int kk = id / C4, c4 = id % C4;
                rb[i] = *(const float4*)(W + (size_t)((s + 1) * KT + kk) * NOUT + bn0 + c4 * 4);
            }
        }
        #pragma unroll
        for (int kk = 0; kk < KT; kk++) {
            u64 ap2[4];
            {
                const ulonglong2* aa = (const ulonglong2*)&sm.mm.As[buf][kk][ty * 8];
                ulonglong2 t0 = aa[0];
                ulonglong2 t1 = aa[1];
                ap2[0] = t0.x; ap2[1] = t0.y; ap2[2] = t1.x; ap2[3] = t1.y;
            }
            float b[MN];
            #pragma unroll
            for (int j = 0; j < MN; j += 4)
                *(float4*)(b + j) = *(const float4*)&sm.mm.Bs[buf][kk][tx * MN + j];
            #pragma unroll
            for (int j = 0; j < MN; j++) {
                u64 bd = dup2(b[j]);
                #pragma unroll
                for (int ip = 0; ip < 4; ip++)
                    fma2(c2[ip][j], ap2[ip], bd);
            }
        }
        if (s + 1 < S) {
            float v[8] = {ra0.x, ra0.y, ra0.z, ra0.w, ra1.x, ra1.y, ra1.z, ra1.w};
            int kb = (s + 1) * KT + ah * 8;
            #pragma unroll
            for (int j = 0; j < 8; j++) {
                float f = fmaf(v[j], s_sc[kb + j], s_sh[kb + j]);
                if (RELU_IN) f = fmaxf(f, 0.f);
                sm.mm.As[buf ^ 1][ah * 8 + j][ar] = mval ? f : 0.f;
            }
            #pragma unroll
            for (int i = 0; i < NB4; i++) {
                int id = t + i * 256;
                int kk = id / C4, c4 = id % C4;
                *(float4*)&sm.mm.Bs[buf ^ 1][kk][c4 * 4] = rb[i];
            }
            __syncthreads();
        }
    }

    float c[8][MN];
    #pragma unroll
    for (int ip = 0; ip < 4; ip++)
        #pragma unroll
        for (int j = 0; j < MN; j++)
            unpack2(c[2 * ip][j], c[2 * ip + 1][j], c2[ip][j]);

    float bb[MN];
    #pragma unroll
    for (int j = 0; j < MN; j++) bb[j] = bias[bn0 + tx * MN + j];
    #pragma unroll
    for (int i = 0; i < 8; i++)
        #pragma unroll
        for (int j = 0; j < MN; j++) c[i][j] += bb[j];

    float cs[MN], cq[MN];
    #pragma unroll
    for (int j = 0; j < MN; j++) { cs[j] = 0.f; cq[j] = 0.f; }
    #pragma unroll
    for (int i = 0; i < 8; i++) {
        long g2 = bm0 + ty * 8 + i;
        if (g2 < N_PTS) {
            float* op = Hout + (size_t)g2 * NOUT + bn0 + tx * MN;
            #pragma unroll
            for (int j = 0; j < MN; j += 4)
                *(float4*)(op + j) = make_float4(c[i][j], c[i][j + 1], c[i][j + 2], c[i][j + 3]);
            #pragma unroll
            for (int j = 0; j < MN; j++) { cs[j] += c[i][j]; cq[j] += c[i][j] * c[i][j]; }
        }
    }
    __syncthreads();
    #pragma unroll
    for (int j = 0; j < MN; j++) {
        sm.red.r1[ty][tx * MN + j] = cs[j];
        sm.red.r2[ty][tx * MN + j] = cq[j];
    }
    __syncthreads();
    if (t < 2 * TN) {
        int col = t & (TN - 1);
        float acc = 0.f;
        if (t < TN) {
            #pragma unroll
            for (int r = 0; r < 16; r++) acc += sm.red.r1[r][col];
            atomicAdd(&g_sum[sslot][bn0 + col], (double)acc);
        } else {
            #pragma unroll
            for (int r = 0; r < 16; r++) acc += sm.red.r2[r][col];
            atomicAdd(&g_sqs[sslot][bn0 + col], (double)acc);
        }
    }
}

// ============== pipelined mma.sync bf16 split GEMM (layers 2-4) ==============
// Block 64 rows x NOUT cols, 8 warps, K chunk 32, double-buffered smem,
// cp.async for B, register prefetch for A. 3-term split Ah*Bh + Ah*Bl + Al*Bh.
// POOL: rows gathered in sorted-voxel order (g_perm); epilogue does in-block
// segmented max -> pool (plain store for interior voxels, atomicMaxF at edges).
#define SA_H 0          /* 2 stages x 5120 */
#define SA_L 10240      /* 2 stages x 5120 */
#define SB_H 20480      /* 2 stages x 20480 */
#define SB_L 61440      /* 2 stages x 20480 */
#define SBIA 102400
#define SCS  103424
#define SCQ  104448
#define SSC  105472
#define SSH  106496
#define SM_MMA_BYTES 107520
// POOL epilogue overlays (A/B tiles dead by then): sout 64x260 f32, sv 64 ints
#define SOUT 0
#define SSV  66560

__device__ __forceinline__ void st8bf(char* base, u32 off, u32 w0, u32 w1, u32 w2, u32 w3) {
    *(uint2*)(base + off)     = make_uint2(w0, w1);
    *(uint2*)(base + off + 8) = make_uint2(w2, w3);
}

template<int KTOT, int NOUT, bool STATS, bool POOL>
__global__ void __launch_bounds__(256, 2)
k_mma(const float* __restrict__ A,
      const __nv_bfloat16* __restrict__ Bh, const __nv_bfloat16* __restrict__ Bl,
      const float* __restrict__ bias, int aslot, int sslot, float* __restrict__ Hout)
{
    constexpr int NC  = KTOT / 32;
    constexpr int WN  = NOUT / 64;      // warps along n (2 or 4)
    constexpr int MT  = WN / 2;         // m16 tiles per warp (1 or 2)
    constexpr int BCH = NOUT / 64;      // cp.async 16B chunks per thread per precision

    extern __shared__ char S[];
    const u32 sb = smem_to_u32(S);
    const int t = threadIdx.x, lane = t & 31, wid = t >> 5;
    const int wm = wid / WN, wn = wid % WN;
    const long gm0 = (long)blockIdx.x * 64;     // 600000 = 64*9375: no edge

    if (t < NOUT) ((float*)(S + SBIA))[t] = bias[t];
    for (int i = t; i < KTOT; i += 256) {
        ((float*)(S + SSC))[i] = g_scale[aslot][i];
        ((float*)(S + SSH))[i] = g_shift[aslot][i];
    }
    if (STATS && t < NOUT) { ((float*)(S + SCS))[t] = 0.f; ((float*)(S + SCQ))[t] = 0.f; }

    float acc[MT][8][4];
    #pragma unroll
    for (int mt = 0; mt < MT; mt++)
        #pragma unroll
        for (int nt = 0; nt < 8; nt++)
            #pragma unroll
            for (int r = 0; r < 4; r++) acc[mt][nt][r] = 0.f;

    const int arow = t >> 2, aseg = t & 3;
    long grow = POOL ? (long)g_perm[gm0 + arow] : (gm0 + arow);
    const float* aP = A + (size_t)grow * KTOT + aseg * 8;

    // ---- prologue: B stage 0 via cp.async, then A stage 0 ----
    #pragma unroll
    for (int it = 0; it < BCH; it++) {
        int id = t + it * 256;
        int row = id >> 2, j = id & 3;
        u32 doff = (u32)(row * 80 + j * 16);
        const __nv_bfloat16* sh = Bh + (size_t)row * KTOT + j * 8;
        const __nv_bfloat16* sl = Bl + (size_t)row * KTOT + j * 8;
        cpasync16(sb + SB_H + doff, sh);
        cpasync16(sb + SB_L + doff, sl);
    }
    CP_COMMIT();
    __syncthreads();    // scale/shift visible before convert
    {
        float4 f0 = *(const float4*)aP, f1 = *(const float4*)(aP + 4);
        float f[8] = {f0.x, f0.y, f0.z, f0.w, f1.x, f1.y, f1.z, f1.w};
        u32 hw[4], lw[4];
        int kb = aseg * 8;
        #pragma unroll
        for (int j = 0; j < 8; j += 2) {
            float a0 = fmaxf(fmaf(f[j],     ((float*)(S + SSC))[kb + j],     ((float*)(S + SSH))[kb + j]),     0.f);
            float a1 = fmaxf(fmaf(f[j + 1], ((float*)(S + SSC))[kb + j + 1], ((float*)(S + SSH))[kb + j + 1]), 0.f);
            __nv_bfloat16 h0 = __float2bfloat16(a0), h1 = __float2bfloat16(a1);
            __nv_bfloat16 l0 = __float2bfloat16(a0 - __bfloat162float(h0));
            __nv_bfloat16 l1 = __float2bfloat16(a1 - __bfloat162float(h1));
            hw[j >> 1] = (u32)__bfloat16_as_ushort(h0) | ((u32)__bfloat16_as_ushort(h1) << 16);
            lw[j >> 1] = (u32)__bfloat16_as_ushort(l0) | ((u32)__bfloat16_as_ushort(l1) << 16);
        }
        u32 off = (u32)(arow * 80 + aseg * 16);
        st8bf(S + SA_H, off, hw[0], hw[1], hw[2], hw[3]);
        st8bf(S + SA_L, off, lw[0], lw[1], lw[2], lw[3]);
    }
    CP_WAIT0();
    __syncthreads();

    for (int c = 0; c < NC; c++) {
        const int buf = c & 1;
        float4 f0, f1;
        if (c + 1 < NC) {
            // issue next B (cp.async) and next A (LDG) before MMA
            #pragma unroll
            for (int it = 0; it < BCH; it++) {
                int id = t + it * 256;
                int row = id >> 2, j = id & 3;
                u32 doff = (u32)((buf ^ 1) * 20480 + row * 80 + j * 16);
                const __nv_bfloat16* sh = Bh + (size_t)row * KTOT + (c + 1) * 32 + j * 8;
                const __nv_bfloat16* sl = Bl + (size_t)row * KTOT + (c + 1) * 32 + j * 8;
                cpasync16(sb + SB_H + doff, sh);
                cpasync16(sb + SB_L + doff, sl);
            }
            CP_COMMIT();
            const float* ap = aP + (c + 1) * 32;
            f0 = *(const float4*)ap; f1 = *(const float4*)(ap + 4);
        }
        // ---- MMA on stage buf ----
        {
            const u32 aBase = sb + SA_H + buf * 5120;
            const u32 bBase = sb + SB_H + buf * 20480;
            #pragma unroll
            for (int ks = 0; ks < 2; ks++) {
                u32 ah[MT][4], al[MT][4];
                #pragma unroll
                for (int mt = 0; mt < MT; mt++) {
                    int mr = (wm * MT + mt) * 16;
                    u32 aaddr = aBase + (u32)(mr + (lane & 15)) * 80u + (u32)(((lane >> 4) * 8 + ks * 16) * 2);
                    ldmx4(ah[mt], aaddr);
                    ldmx4(al[mt], aaddr + 10240);
                }
                #pragma unroll
                for (int ntp = 0; ntp < 4; ntp++) {
                    int n0 = wn * 64 + ntp * 16;
                    u32 baddr = bBase + (u32)(n0 + (lane & 7) + ((lane >> 4) << 3)) * 80u
                              + (u32)(((((lane >> 3) & 1) * 8) + ks * 16) * 2);
                    u32 bh4[4], bl4[4];
                    ldmx4(bh4, baddr);
                    ldmx4(bl4, baddr + 40960);
                    #pragma unroll
                    for (int mt = 0; mt < MT; mt++) {
                        mma16816(acc[mt][2 * ntp],     ah[mt], bh4[0], bh4[1]);
                        mma16816(acc[mt][2 * ntp],     ah[mt], bl4[0], bl4[1]);
                        mma16816(acc[mt][2 * ntp],     al[mt], bh4[0], bh4[1]);
                        mma16816(acc[mt][2 * ntp + 1], ah[mt], bh4[2], bh4[3]);
                        mma16816(acc[mt][2 * ntp + 1], ah[mt], bl4[2], bl4[3]);
                        mma16816(acc[mt][2 * ntp + 1], al[mt], bh4[2], bh4[3]);
                    }
                }
            }
        }
        if (c + 1 < NC) {
            // convert + store next A into stage buf^1
            float f[8] = {f0.x, f0.y, f0.z, f0.w, f1.x, f1.y, f1.z, f1.w};
            u32 hw[4], lw[4];
            int kb = (c + 1) * 32 + aseg * 8;
            #pragma unroll
            for (int j = 0; j < 8; j += 2) {
                float a0 = fmaxf(fmaf(f[j],     ((float*)(S + SSC))[kb + j],     ((float*)(S + SSH))[kb + j]),     0.f);
                float a1 = fmaxf(fmaf(f[j + 1], ((float*)(S + SSC))[kb + j + 1], ((float*)(S + SSH))[kb + j + 1]), 0.f);
                __nv_bfloat16 h0 = __float2bfloat16(a0), h1 = __float2bfloat16(a1);
                __nv_bfloat16 l0 = __float2bfloat16(a0 - __bfloat162float(h0));
                __nv_bfloat16 l1 = __float2bfloat16(a1 - __bfloat162float(h1));
                hw[j >> 1] = (u32)__bfloat16_as_ushort(h0) | ((u32)__bfloat16_as_ushort(h1) << 16);
                lw[j >> 1] = (u32)__bfloat16_as_ushort(l0) | ((u32)__bfloat16_as_ushort(l1) << 16);
            }
            u32 off = (u32)((buf ^ 1) * 5120 + arow * 80 + aseg * 16);
            st8bf(S + SA_H, off, hw[0], hw[1], hw[2], hw[3]);
            st8bf(S + SA_L, off, lw[0], lw[1], lw[2], lw[3]);
            CP_WAIT0();
            __syncthreads();
        }
    }

    // ---- epilogue: bias ----
    const int cq = (lane & 3) * 2, rq = lane >> 2;
    #pragma unroll
    for (int mt = 0; mt < MT; mt++)
        #pragma unroll
        for (int nt = 0; nt < 8; nt++) {
            int col = wn * 64 + nt * 8 + cq;
            float b0 = ((float*)(S + SBIA))[col], b1 = ((float*)(S + SBIA))[col + 1];
            acc[mt][nt][0] += b0; acc[mt][nt][1] += b1;
            acc[mt][nt][2] += b0; acc[mt][nt][3] += b1;
        }

    if (POOL) {
        // stage tile in smem (A/B buffers dead), then per-column segmented max
        __syncthreads();
        float* sout = (float*)(S + SOUT);           // [64][260]
        #pragma unroll
        for (int mt = 0; mt < MT; mt++) {
            int r0 = (wm * MT + mt) * 16 + rq;
            #pragma unroll
            for (int nt = 0; nt < 8; nt++) {
                int col = wn * 64 + nt * 8 + cq;
                float* d = acc[mt][nt];
                *(float2*)&sout[r0 * 260 + col]       = make_float2(d[0], d[1]);
                *(float2*)&sout[(r0 + 8) * 260 + col] = make_float2(d[2], d[3]);
            }
        }
        if (t < 64) ((int*)(S + SSV))[t] = g_svox[gm0 + t];
        __syncthreads();
        const int* sv = (const int*)(S + SSV);
        int c = t;                                   // column 0..255
        int p = 0;
        while (p < 64) {
            int v = sv[p];
            int q = p + 1;
            while (q < 64 && sv[q] == v) q++;
            float m = -3.402823466e38f;
            for (int r = p; r < q; r++) m = fmaxf(m, sout[r * 260 + c]);
            int gs = g_start[v], ge = g_start[v + 1];
            float* pp = g_pool + (size_t)v * 256 + c;
            if (gs == (int)gm0 + p && ge == (int)gm0 + q) *pp = m;   // interior: sole owner
            else atomicMaxF(pp, m);                                  // boundary voxel
            p = q;
        }
    } else {
        #pragma unroll
        for (int mt = 0; mt < MT; mt++) {
            long r0 = gm0 + (wm * MT + mt) * 16 + rq;
            #pragma unroll
            for (int nt = 0; nt < 8; nt++) {
                int col = wn * 64 + nt * 8 + cq;
                float* d = acc[mt][nt];
                *(float2*)&Hout[(size_t)r0 * NOUT + col]       = make_float2(d[0], d[1]);
                *(float2*)&Hout[(size_t)(r0 + 8) * NOUT + col] = make_float2(d[2], d[3]);
            }
        }
    }
    if (STATS) {
        #pragma unroll
        for (int nt = 0; nt < 8; nt++) {
            float s0 = 0.f, s1 = 0.f, q0 = 0.f, q1 = 0.f;
            #pragma unroll
            for (int mt = 0; mt < MT; mt++) {
                float* d = acc[mt][nt];
                s0 += d[0] + d[2]; s1 += d[1] + d[3];
                q0 += d[0] * d[0] + d[2] * d[2];
                q1 += d[1] * d[1] + d[3] * d[3];
            }
            #pragma unroll
            for (int o = 4; o < 32; o <<= 1) {
                s0 += __shfl_xor_sync(0xFFFFFFFFu, s0, o);
                s1 += __shfl_xor_sync(0xFFFFFFFFu, s1, o);
                q0 += __shfl_xor_sync(0xFFFFFFFFu, q0, o);
                q1 += __shfl_xor_sync(0xFFFFFFFFu, q1, o);
            }
            if (rq == 0) {
                int col = wn * 64 + nt * 8 + cq;
                atomicAdd(&((float*)(S + SCS))[col], s0);
                atomicAdd(&((float*)(S + SCS))[col + 1], s1);
                atomicAdd(&((float*)(S + SCQ))[col], q0);
                atomicAdd(&((float*)(S + SCQ))[col + 1], q1);
            }
        }
        __syncthreads();
        if (t < NOUT) {
            atomicAdd(&g_sum[sslot][t], (double)((float*)(S + SCS))[t]);
            atomicAdd(&g_sqs[sslot][t], (double)((float*)(S + SCQ))[t]);
        }
    }
}

// ===================== final: relu(where(finite(pool),pool,0) @ wc + bc) =====================
__global__ void __launch_bounds__(64)
k_final(const float* __restrict__ wc, const float* __restrict__ bc, float* __restrict__ out)
{
    __shared__ float s_in[16][260];
    __shared__ float s_w[256][16];
    __shared__ float s_b[16];
    int t = threadIdx.x;
    long v0 = (long)blockIdx.x * 16;
    for (int i = t; i < 4096; i += 64) s_w[i >> 4][i & 15] = wc[i];
    if (t < 16) s_b[t] = bc[t];
    for (int i = t; i < 4096; i += 64) {
        int rr = i >> 8, cc = i & 255;
        long v = v0 + rr;
        float x = 0.f;
        if (v < N_VOX) {
            x = g_pool[(size_t)v * 256 + cc];
            if (!isfinite(x)) x = 0.f;
        }
        s_in[rr][cc] = x;
    }
    __syncthreads();
    int r = t >> 2, o = (t & 3) * 4;
    float a0 = s_b[o], a1 = s_b[o + 1], a2 = s_b[o + 2], a3 = s_b[o + 3];
    #pragma unroll 8
    for (int k = 0; k < 256; k++) {
        float x = s_in[r][k];
        float4 w = *(const float4*)&s_w[k][o];
        a0 = fmaf(x, w.x, a0); a1 = fmaf(x, w.y, a1);
        a2 = fmaf(x, w.z, a2); a3 = fmaf(x, w.w, a3);
    }
    long v = v0 + r;
    if (v < N_VOX) {
        float4 res = make_float4(fmaxf(a0, 0.f), fmaxf(a1, 0.f), fmaxf(a2, 0.f), fmaxf(a3, 0.f));
        *(float4*)&out[(size_t)v * 16 + o] = res;
    }
}

// ===================== launch =====================
extern "C" void kernel_launch(void* const* d_in, const int* in_sizes, int n_in,
                              void* d_out, int out_size)
{
    const float* pt   = (const float*)d_in[0];
    const float* bn0g = (const float*)d_in[1];
    const float* bn0b = (const float*)d_in[2];
    const float* w1   = (const float*)d_in[3];
    const float* b1   = (const float*)d_in[4];
    const float* bn1g = (const float*)d_in[5];
    const float* bn1b = (const float*)d_in[6];
    const float* w2   = (const float*)d_in[7];
    const float* b2   = (const float*)d_in[8];
    const float* bn2g = (const float*)d_in[9];
    const float* bn2b = (const float*)d_in[10];
    const float* w3   = (const float*)d_in[11];
    const float* b3   = (const float*)d_in[12];
    const float* bn3g = (const float*)d_in[13];
    const float* bn3b = (const float*)d_in[14];
    const float* w4   = (const float*)d_in[15];
    const float* b4   = (const float*)d_in[16];
    const float* wc   = (const float*)d_in[17];
    const float* bc   = (const float*)d_in[18];
    const int*   uinv = (const int*)d_in[19];
    float* out = (float*)d_out;

    float *h1, *h2, *h3;
    __nv_bfloat16 *w2h, *w2l, *w3h, *w3l, *w4h, *w4l;
    cudaGetSymbolAddress((void**)&h1, g_h1);
    cudaGetSymbolAddress((void**)&h2, g_h2);
    cudaGetSymbolAddress((void**)&h3, g_h3);
    cudaGetSymbolAddress((void**)&w2h, g_w2h);
    cudaGetSymbolAddress((void**)&w2l, g_w2l);
    cudaGetSymbolAddress((void**)&w3h, g_w3h);
    cudaGetSymbolAddress((void**)&w3l, g_w3l);
    cudaGetSymbolAddress((void**)&w4h, g_w4h);
    cudaGetSymbolAddress((void**)&w4l, g_w4l);

    cudaFuncSetAttribute(k_mma<64, 128, true, false>,   cudaFuncAttributeMaxDynamicSharedMemorySize, SM_MMA_BYTES);
    cudaFuncSetAttribute(k_mma<128, 256, true, false>,  cudaFuncAttributeMaxDynamicSharedMemorySize, SM_MMA_BYTES);
    cudaFuncSetAttribute(k_mma<256, 256, false, true>,  cudaFuncAttributeMaxDynamicSharedMemorySize, SM_MMA_BYTES);

    const int GM = (N_PTS + 127) / 128;   // 4688 (layer 1)
    const int GB = N_PTS / 64;            // 9375 (layers 2-4, exact)
    const int NSB = (N_VOX + SCB - 1) / SCB;   // 391 scan blocks

    k_zero_stats<<<1, 256>>>();
    k_zero_cnt<<<(N_VOX + 255) / 256, 256>>>();
    k_fill_pool<<<2048, 256>>>();
    k_stats_in<<<1024, 256>>>(pt);
    k_wprep<<<416, 256>>>(w2, w3, w4);
    k_hist<<<(N_PTS + 255) / 256, 256>>>(uinv);
    k_scan1<<<NSB, SCB>>>();
    k_scan2<<<1, SCB>>>(NSB);
    k_scan3<<<NSB, SCB>>>();
    k_scatter<<<(N_PTS + 255) / 256, 256>>>(uinv);
    k_prep<<<1, 256>>>(bn0g, bn0b, 0, 16);
    k_gemm<16, 64, false><<<dim3(1, GM), 256>>>(pt, w1, b1, 64, 0, 1, h1);
    k_prep<<<1, 256>>>(bn1g, bn1b, 1, 64);
    k_mma<64, 128, true, false><<<GB, 256, SM_MMA_BYTES>>>(h1, w2h, w2l, b2, 1, 2, h2);
    k_prep<<<1, 256>>>(bn2g, bn2b, 2, 128);
    k_mma<128, 256, true, false><<<GB, 256, SM_MMA_BYTES>>>(h2, w3h, w3l, b3, 2, 3, h3);
    k_prep<<<1, 256>>>(bn3g, bn3b, 3, 256);
    k_mma<256, 256, false, true><<<GB, 256, SM_MMA_BYTES>>>(h3, w4h, w4l, b4, 3, 0, nullptr);
    k_final<<<(N_VOX + 15) / 16, 64>>>(wc, bc, out);
}

// round 8
// speedup vs baseline: 1.6556x; 1.6556x over previous
#include <cuda_runtime.h>
#include <cuda_fp16.h>
#include <cstdint>
#include <math.h>

#define N_PTS 600000
#define N_VOX 200000
typedef unsigned long long u64;
typedef unsigned int u32;

// ===================== PTX helpers (family-agnostic, sm_100-safe) =====================
__device__ __forceinline__ u32 smem_to_u32(const void* p) {
    u32 a;
    asm("{ .reg .u64 tmp; cvta.to.shared.u64 tmp, %1; cvt.u32.u64 %0, tmp; }" : "=r"(a) : "l"(p));
    return a;
}
__device__ __forceinline__ void ldmx4(u32* r, u32 addr) {
    asm volatile("ldmatrix.sync.aligned.m8n8.x4.shared.b16 {%0,%1,%2,%3}, [%4];"
        : "=r"(r[0]), "=r"(r[1]), "=r"(r[2]), "=r"(r[3]) : "r"(addr));
}
__device__ __forceinline__ void mma16816(float* d, const u32* a, u32 b0, u32 b1) {
    asm volatile("mma.sync.aligned.m16n8k16.row.col.f32.f16.f16.f32 "
        "{%0,%1,%2,%3}, {%4,%5,%6,%7}, {%8,%9}, {%0,%1,%2,%3};"
        : "+f"(d[0]), "+f"(d[1]), "+f"(d[2]), "+f"(d[3])
        : "r"(a[0]), "r"(a[1]), "r"(a[2]), "r"(a[3]), "r"(b0), "r"(b1));
}
__device__ __forceinline__ void cpasync16(u32 dst, const void* src) {
    asm volatile("cp.async.cg.shared.global [%0], [%1], 16;" :: "r"(dst), "l"(src));
}
#define CP_COMMIT() asm volatile("cp.async.commit_group;" ::: "memory")
#define CP_WAIT0()  asm volatile("cp.async.wait_group 0;" ::: "memory")
// packed f32x2 helpers for the FFMA GEMM (layer 1)
__device__ __forceinline__ u64 dup2(float x) { u64 r; asm("mov.b64 %0, {%1, %1};" : "=l"(r) : "f"(x)); return r; }
__device__ __forceinline__ void fma2(u64& d, u64 a, u64 b) { asm("fma.rn.f32x2 %0, %1, %2, %0;" : "+l"(d) : "l"(a), "l"(b)); }
__device__ __forceinline__ void unpack2(float& lo, float& hi, u64 v) { asm("mov.b64 {%0, %1}, %2;" : "=f"(lo), "=f"(hi) : "l"(v)); }

// ===================== static device scratch =====================
static __device__ __align__(16) __half g_h1[(size_t)N_PTS * 64];
static __device__ __align__(16) __half g_h2[(size_t)N_PTS * 128];
static __device__ __align__(16) __half g_h3[(size_t)N_PTS * 256];
static __device__ __align__(16) __half g_h4[(size_t)N_PTS * 256];
static __device__ double g_sum[4][256];
static __device__ double g_sqs[4][256];
static __device__ float  g_scale[4][256];
static __device__ float  g_shift[4][256];
static __device__ __align__(16) __half g_w2[8192];    // [n=128][k=64]
static __device__ __align__(16) __half g_w3[32768];   // [n=256][k=128]
static __device__ __align__(16) __half g_w4[65536];   // [n=256][k=256]
static __device__ int g_cnt[N_VOX];
static __device__ int g_start[N_VOX + 1];
static __device__ int g_bsum[512];
static __device__ int g_perm[N_PTS];

// ===================== small utility kernels =====================
__global__ void k_init() {
    int i = blockIdx.x * blockDim.x + threadIdx.x;
    if (i < N_VOX) g_cnt[i] = 0;
    if (i < 256)
        for (int s = 0; s < 4; s++) { g_sum[s][i] = 0.0; g_sqs[s][i] = 0.0; }
}
__global__ void k_stats_in(const float* __restrict__ x) {
    int t = threadIdx.x;
    int col = t & 15;
    float s = 0.f, q = 0.f;
    size_t i = (size_t)blockIdx.x * blockDim.x + t;
    size_t stride = (size_t)gridDim.x * blockDim.x;
    const size_t total = (size_t)N_PTS * 16;
    for (; i < total; i += stride) { float v = x[i]; s += v; q += v * v; }
    __shared__ float ss[16][16], qq[16][16];
    ss[t >> 4][col] = s; qq[t >> 4][col] = q;
    __syncthreads();
    if (t < 16) {
        float S = 0.f, Q = 0.f;
        #pragma unroll
        for (int r = 0; r < 16; r++) { S += ss[r][t]; Q += qq[r][t]; }
        atomicAdd(&g_sum[0][t], (double)S);
        atomicAdd(&g_sqs[0][t], (double)Q);
    }
}
__global__ void k_prep(const float* __restrict__ g, const float* __restrict__ b, int slot, int C) {
    int t = blockIdx.x * blockDim.x + threadIdx.x;
    if (t >= C) return;
    double mean = g_sum[slot][t] / (double)N_PTS;
    double var  = g_sqs[slot][t] / (double)N_PTS - mean * mean;
    float inv = (float)(1.0 / sqrt(var + 1e-5));
    float sc = g[t] * inv;
    g_scale[slot][t] = sc;
    g_shift[slot][t] = b[t] - (float)mean * sc;
}

// Pre-transpose + fp16 convert of W2/W3/W4 into [n][k] row-major images.
__global__ void k_wprep(const float* __restrict__ w2, const float* __restrict__ w3,
                        const float* __restrict__ w4) {
    int i = blockIdx.x * 256 + threadIdx.x;
    if (i < 8192) {                                  // layer 2: K=64, N=128
        int n = i >> 6, k = i & 63;
        g_w2[i] = __float2half(w2[k * 128 + n]);
    } else if (i < 8192 + 32768) {                   // layer 3: K=128, N=256
        int j = i - 8192;
        int n = j >> 7, k = j & 127;
        g_w3[j] = __float2half(w3[k * 256 + n]);
    } else if (i < 8192 + 32768 + 65536) {           // layer 4: K=256, N=256
        int j = i - 40960;
        int n = j >> 8, k = j & 255;
        g_w4[j] = __float2half(w4[k * 256 + n]);
    }
}

// ===================== counting sort by voxel =====================
__global__ void k_hist(const int* __restrict__ uinv) {
    int i = blockIdx.x * blockDim.x + threadIdx.x;
    if (i < N_PTS) atomicAdd(&g_cnt[uinv[i]], 1);
}
#define SCB 512
__global__ void k_scan1() {
    int t = threadIdx.x, b = blockIdx.x;
    int i = b * SCB + t;
    int x = (i < N_VOX) ? g_cnt[i] : 0;
    __shared__ int sc[SCB];
    sc[t] = x; __syncthreads();
    for (int ofs = 1; ofs < SCB; ofs <<= 1) {
        int y = (t >= ofs) ? sc[t - ofs] : 0;
        __syncthreads();
        sc[t] += y;
        __syncthreads();
    }
    if (i < N_VOX) g_start[i] = sc[t] - x;
    if (t == SCB - 1) g_bsum[b] = sc[t];
}
__global__ void k_scan2(int nblk) {
    int t = threadIdx.x;
    int x = (t < nblk) ? g_bsum[t] : 0;
    __shared__ int sc[SCB];
    sc[t] = x; __syncthreads();
    for (int ofs = 1; ofs < SCB; ofs <<= 1) {
        int y = (t >= ofs) ? sc[t - ofs] : 0;
        __syncthreads();
        sc[t] += y;
        __syncthreads();
    }
    if (t < nblk) g_bsum[t] = sc[t] - x;
}
__global__ void k_scan3() {
    int t = threadIdx.x, b = blockIdx.x;
    int i = b * SCB + t;
    if (i < N_VOX) g_start[i] += g_bsum[b];
    if (i == 0) g_start[N_VOX] = N_PTS;
}
__global__ void k_scatter(const int* __restrict__ uinv) {
    int i = blockIdx.x * blockDim.x + threadIdx.x;
    if (i < N_PTS) {
        int v = uinv[i];
        int old = atomicAdd(&g_cnt[v], -1);
        g_perm[g_start[v] + old - 1] = i;
    }
}

// ===================== FFMA GEMM (layer 1, fp32 compute, fp16 store) =====================
template<int K, int TN, bool RELU_IN>
__global__ void __launch_bounds__(256)
k_gemm(const float* __restrict__ A, const float* __restrict__ W,
       const float* __restrict__ bias, int NOUT, int aslot, int sslot,
       __half* __restrict__ Hout)
{
    constexpr int TM = 128, KT = 16;
    constexpr int MN = TN / 16;
    constexpr int S  = K / KT;
    constexpr int NB4 = (KT * TN) / (4 * 256);
    constexpr int C4  = TN / 4;

    __shared__ union SmemU {
        struct { float As[2][KT][TM]; float Bs[2][KT][TN]; } mm;
        struct { float r1[16][TN]; float r2[16][TN]; } red;
    } sm;
    __shared__ float s_sc[K], s_sh[K];

    const int t  = threadIdx.x;
    const int tx = t & 15, ty = t >> 4;
    const int bn0 = blockIdx.x * TN;
    const long bm0 = (long)blockIdx.y * TM;

    for (int i = t; i < K; i += 256) { s_sc[i] = g_scale[aslot][i]; s_sh[i] = g_shift[aslot][i]; }

    const int  ar = t & 127;
    const int  ah = t >> 7;
    const long gm = bm0 + ar;
    const bool mval = gm < N_PTS;
    const float* aptr = A + (size_t)(mval ? gm : 0) * K + ah * 8;

    u64 c2[4][MN];
    #pragma unroll
    for (int i = 0; i < 4; i++)
        #pragma unroll
        for (int j = 0; j < MN; j++) c2[i][j] = 0ull;

    float4 ra0, ra1, rb[NB4];
    ra0 = make_float4(0.f, 0.f, 0.f, 0.f); ra1 = ra0;
    if (mval) { ra0 = *(const float4*)(aptr); ra1 = *(const float4*)(aptr + 4); }
    #pragma unroll
    for (int i = 0; i < NB4; i++) {
        int id = t + i * 256;
        int kk = id / C4, c4 = id % C4;
        rb[i] = *(const float4*)(W + (size_t)kk * NOUT + bn0 + c4 * 4);
    }
    __syncthreads();
    {
        float v[8] = {ra0.x, ra0.y, ra0.z, ra0.w, ra1.x, ra1.y, ra1.z, ra1.w};
        #pragma unroll
        for (int j = 0; j < 8; j++) {
            int k = ah * 8 + j;
            float f = fmaf(v[j], s_sc[k], s_sh[k]);
            if (RELU_IN) f = fmaxf(f, 0.f);
            sm.mm.As[0][ah * 8 + j][ar] = mval ? f : 0.f;
        }
        #pragma unroll
        for (int i = 0; i < NB4; i++) {
            int id = t + i * 256;
            int kk = id / C4, c4 = id % C4;
            *(float4*)&sm.mm.Bs[0][kk][c4 * 4] = rb[i];
        }
    }
    __syncthreads();

    for (int s = 0; s < S; s++) {
        const int buf = s & 1;
        if (s + 1 < S) {
            const float* ap = aptr + (s + 1) * KT;
            ra0 = make_float4(0.f, 0.f, 0.f, 0.f); ra1 = ra0;
            if (mval) { ra0 = *(const float4*)ap; ra1 = *(const float4*)(ap + 4); }
            #pragma unroll
            for (int i = 0; i < NB4; i++) {
                int id = t + i * 256;
                int kk = id / C4, c4 = id % C4;
                rb[i] = *(const float4*)(W + (size_t)((s + 1) * KT + kk) * NOUT + bn0 + c4 * 4);
            }
        }
        #pragma unroll
        for (int kk = 0; kk < KT; kk++) {
            u64 ap2[4];
            {
                const ulonglong2* aa = (const ulonglong2*)&sm.mm.As[buf][kk][ty * 8];
                ulonglong2 t0 = aa[0];
                ulonglong2 t1 = aa[1];
                ap2[0] = t0.x; ap2[1] = t0.y; ap2[2] = t1.x; ap2[3] = t1.y;
            }
            float b[MN];
            #pragma unroll
            for (int j = 0; j < MN; j += 4)
                *(float4*)(b + j) = *(const float4*)&sm.mm.Bs[buf][kk][tx * MN + j];
            #pragma unroll
            for (int j = 0; j < MN; j++) {
                u64 bd = dup2(b[j]);
                #pragma unroll
                for (int ip = 0; ip < 4; ip++)
                    fma2(c2[ip][j], ap2[ip], bd);
            }
        }
        if (s + 1 < S) {
            float v[8] = {ra0.x, ra0.y, ra0.z, ra0.w, ra1.x, ra1.y, ra1.z, ra1.w};
            int kb = (s + 1) * KT + ah * 8;
            #pragma unroll
            for (int j = 0; j < 8; j++) {
                float f = fmaf(v[j], s_sc[kb + j], s_sh[kb + j]);
                if (RELU_IN) f = fmaxf(f, 0.f);
                sm.mm.As[buf ^ 1][ah * 8 + j][ar] = mval ? f : 0.f;
            }
            #pragma unroll
            for (int i = 0; i < NB4; i++) {
                int id = t + i * 256;
                int kk = id / C4, c4 = id % C4;
                *(float4*)&sm.mm.Bs[buf ^ 1][kk][c4 * 4] = rb[i];
            }
            __syncthreads();
        }
    }

    float c[8][MN];
    #pragma unroll
    for (int ip = 0; ip < 4; ip++)
        #pragma unroll
        for (int j = 0; j < MN; j++)
            unpack2(c[2 * ip][j], c[2 * ip + 1][j], c2[ip][j]);

    float bb[MN];
    #pragma unroll
    for (int j = 0; j < MN; j++) bb[j] = bias[bn0 + tx * MN + j];
    #pragma unroll
    for (int i = 0; i < 8; i++)
        #pragma unroll
        for (int j = 0; j < MN; j++) c[i][j] += bb[j];

    float cs[MN], cq[MN];
    #pragma unroll
    for (int j = 0; j < MN; j++) { cs[j] = 0.f; cq[j] = 0.f; }
    #pragma unroll
    for (int i = 0; i < 8; i++) {
        long g2 = bm0 + ty * 8 + i;
        if (g2 < N_PTS) {
            __half* op = Hout + (size_t)g2 * NOUT + bn0 + tx * MN;
            #pragma unroll
            for (int j = 0; j < MN; j += 2)
                *(__half2*)(op + j) = __float22half2_rn(make_float2(c[i][j], c[i][j + 1]));
            #pragma unroll
            for (int j = 0; j < MN; j++) { cs[j] += c[i][j]; cq[j] += c[i][j] * c[i][j]; }
        }
    }
    __syncthreads();
    #pragma unroll
    for (int j = 0; j < MN; j++) {
        sm.red.r1[ty][tx * MN + j] = cs[j];
        sm.red.r2[ty][tx * MN + j] = cq[j];
    }
    __syncthreads();
    if (t < 2 * TN) {
        int col = t & (TN - 1);
        float acc = 0.f;
        if (t < TN) {
            #pragma unroll
            for (int r = 0; r < 16; r++) acc += sm.red.r1[r][col];
            atomicAdd(&g_sum[sslot][bn0 + col], (double)acc);
        } else {
            #pragma unroll
            for (int r = 0; r < 16; r++) acc += sm.red.r2[r][col];
            atomicAdd(&g_sqs[sslot][bn0 + col], (double)acc);
        }
    }
}

// ============== pipelined mma.sync fp16 single-term GEMM (layers 2-4) ==============
// Block 64 rows x NOUT cols, 8 warps, K chunk 32, double-buffered smem,
// cp.async for B, register prefetch for A. fp16 in, fp32 accumulate, fp16 out.
__device__ __forceinline__ void cvt_store_a(char* S, u32 sscOff, u32 sshOff,
                                            uint4 v, int kb, u32 dst) {
    const float* sc = (const float*)(S + sscOff);
    const float* sh = (const float*)(S + sshOff);
    __half2 hp[4];
    *(uint4*)hp = v;
    u32 out[4];
    #pragma unroll
    for (int j = 0; j < 4; j++) {
        float2 f = __half22float2(hp[j]);
        int k = kb + 2 * j;
        float a0 = fmaxf(fmaf(f.x, sc[k],     sh[k]),     0.f);
        float a1 = fmaxf(fmaf(f.y, sc[k + 1], sh[k + 1]), 0.f);
        __half2 r = __float22half2_rn(make_float2(a0, a1));
        out[j] = *(u32*)&r;
    }
    *(uint4*)(S + dst) = *(uint4*)out;
}

template<int KTOT, int NOUT, bool STATS>
__global__ void __launch_bounds__(256, 2)
k_mma(const __half* __restrict__ A, const __half* __restrict__ B,
      const float* __restrict__ bias, int aslot, int sslot, __half* __restrict__ Hout)
{
    constexpr int NC   = KTOT / 32;
    constexpr int WN   = NOUT / 64;          // warps along n (2 or 4)
    constexpr int MT   = WN / 2 > 0 ? (8 / (8 / WN)) / WN * (64 / 16) / (8 / WN) : 1; // see below
    // rows per warp = 64 / (8 / WN) ; m16 tiles per warp:
    constexpr int WM   = 8 / WN;             // warps along m
    constexpr int MTT  = (64 / WM) / 16;     // m16 tiles per warp (1 or 2)
    constexpr int BCH  = NOUT / 64;          // cp.async 16B chunks per thread
    constexpr int SB_OFF = 10240;            // A: 2 stages x 5120
    constexpr int SBIA = SB_OFF + 2 * NOUT * 80;
    constexpr int SCS  = SBIA + 1024;
    constexpr int SCQ  = SCS + 1024;
    constexpr int SSC  = SCQ + 1024;
    constexpr int SSH  = SSC + 1024;

    extern __shared__ char S[];
    const u32 sb = smem_to_u32(S);
    const int t = threadIdx.x, lane = t & 31, wid = t >> 5;
    const int wm = wid / WN, wn = wid % WN;
    const long gm0 = (long)blockIdx.x * 64;      // 600000 = 64*9375: no edge

    if (t < NOUT) ((float*)(S + SBIA))[t] = bias[t];
    for (int i = t; i < KTOT; i += 256) {
        ((float*)(S + SSC))[i] = g_scale[aslot][i];
        ((float*)(S + SSH))[i] = g_shift[aslot][i];
    }
    if (STATS && t < NOUT) { ((float*)(S + SCS))[t] = 0.f; ((float*)(S + SCQ))[t] = 0.f; }

    float acc[MTT][8][4];
    #pragma unroll
    for (int mt = 0; mt < MTT; mt++)
        #pragma unroll
        for (int nt = 0; nt < 8; nt++)
            #pragma unroll
            for (int r = 0; r < 4; r++) acc[mt][nt][r] = 0.f;

    const int arow = t >> 2, aseg = t & 3;
    const __half* aP = A + (size_t)(gm0 + arow) * KTOT + aseg * 8;

    // ---- prologue: B stage 0 via cp.async, then A stage 0 ----
    #pragma unroll
    for (int it = 0; it < BCH; it++) {
        int id = t + it * 256;
        int row = id >> 2, j = id & 3;
        cpasync16(sb + SB_OFF + (u32)(row * 80 + j * 16), B + (size_t)row * KTOT + j * 8);
    }
    CP_COMMIT();
    __syncthreads();     // scale/shift visible before convert
    {
        uint4 v = *(const uint4*)aP;
        cvt_store_a(S, SSC, SSH, v, aseg * 8, (u32)(arow * 80 + aseg * 16));
    }
    CP_WAIT0();
    __syncthreads();

    for (int c = 0; c < NC; c++) {
        const int buf = c & 1;
        uint4 va;
        if (c + 1 < NC) {
            #pragma unroll
            for (int it = 0; it < BCH; it++) {
                int id = t + it * 256;
                int row = id >> 2, j = id & 3;
                cpasync16(sb + SB_OFF + (u32)((buf ^ 1) * NOUT * 80 + row * 80 + j * 16),
                          B + (size_t)row * KTOT + (c + 1) * 32 + j * 8);
            }
            CP_COMMIT();
            va = *(const uint4*)(aP + (c + 1) * 32);
        }
        // ---- MMA on stage buf ----
        {
            const u32 aBase = sb + buf * 5120;
            const u32 bBase = sb + SB_OFF + buf * (NOUT * 80);
            #pragma unroll
            for (int ks = 0; ks < 2; ks++) {
                u32 am[MTT][4];
                #pragma unroll
                for (int mt = 0; mt < MTT; mt++) {
                    int mr = (wm * MTT + mt) * 16;
                    u32 aaddr = aBase + (u32)(mr + (lane & 15)) * 80u + (u32)(((lane >> 4) * 8 + ks * 16) * 2);
                    ldmx4(am[mt], aaddr);
                }
                #pragma unroll
                for (int ntp = 0; ntp < 4; ntp++) {
                    int n0 = wn * 64 + ntp * 16;
                    u32 baddr = bBase + (u32)(n0 + (lane & 7) + ((lane >> 4) << 3)) * 80u
                              + (u32)(((((lane >> 3) & 1) * 8) + ks * 16) * 2);
                    u32 bb[4];
                    ldmx4(bb, baddr);
                    #pragma unroll
                    for (int mt = 0; mt < MTT; mt++) {
                        mma16816(acc[mt][2 * ntp],     am[mt], bb[0], bb[1]);
                        mma16816(acc[mt][2 * ntp + 1], am[mt], bb[2], bb[3]);
                    }
                }
            }
        }
        if (c + 1 < NC) {
            cvt_store_a(S, SSC, SSH, va, (c + 1) * 32 + aseg * 8,
                        (u32)((buf ^ 1) * 5120 + arow * 80 + aseg * 16));
            CP_WAIT0();
            __syncthreads();
        }
    }

    // ---- epilogue: bias, fp16 store, optional stats ----
    const int cq = (lane & 3) * 2, rq = lane >> 2;
    #pragma unroll
    for (int mt = 0; mt < MTT; mt++)
        #pragma unroll
        for (int nt = 0; nt < 8; nt++) {
            int col = wn * 64 + nt * 8 + cq;
            float b0 = ((float*)(S + SBIA))[col], b1 = ((float*)(S + SBIA))[col + 1];
            acc[mt][nt][0] += b0; acc[mt][nt][1] += b1;
            acc[mt][nt][2] += b0; acc[mt][nt][3] += b1;
        }
    #pragma unroll
    for (int mt = 0; mt < MTT; mt++) {
        long r0 = gm0 + (wm * MTT + mt) * 16 + rq;
        #pragma unroll
        for (int nt = 0; nt < 8; nt++) {
            int col = wn * 64 + nt * 8 + cq;
            float* d = acc[mt][nt];
            *(__half2*)&Hout[(size_t)r0 * NOUT + col]       = __float22half2_rn(make_float2(d[0], d[1]));
            *(__half2*)&Hout[(size_t)(r0 + 8) * NOUT + col] = __float22half2_rn(make_float2(d[2], d[3]));
        }
    }
    if (STATS) {
        #pragma unroll
        for (int nt = 0; nt < 8; nt++) {
            float s0 = 0.f, s1 = 0.f, q0 = 0.f, q1 = 0.f;
            #pragma unroll
            for (int mt = 0; mt < MTT; mt++) {
                float* d = acc[mt][nt];
                s0 += d[0] + d[2]; s1 += d[1] + d[3];
                q0 += d[0] * d[0] + d[2] * d[2];
                q1 += d[1] * d[1] + d[3] * d[3];
            }
            #pragma unroll
            for (int o = 4; o < 32; o <<= 1) {
                s0 += __shfl_xor_sync(0xFFFFFFFFu, s0, o);
                s1 += __shfl_xor_sync(0xFFFFFFFFu, s1, o);
                q0 += __shfl_xor_sync(0xFFFFFFFFu, q0, o);
                q1 += __shfl_xor_sync(0xFFFFFFFFu, q1, o);
            }
            if (rq == 0) {
                int col = wn * 64 + nt * 8 + cq;
                atomicAdd(&((float*)(S + SCS))[col], s0);
                atomicAdd(&((float*)(S + SCS))[col + 1], s1);
                atomicAdd(&((float*)(S + SCQ))[col], q0);
                atomicAdd(&((float*)(S + SCQ))[col + 1], q1);
            }
        }
        __syncthreads();
        if (t < NOUT) {
            atomicAdd(&g_sum[sslot][t], (double)((float*)(S + SCS))[t]);
            atomicAdd(&g_sqs[sslot][t], (double)((float*)(S + SCQ))[t]);
        }
    }
}

// ============ fused gather-max pool + relu(pool @ wc + bc) ============
// Block: 128 threads, 8 voxels. 16 threads per voxel gather its sorted points
// from g_h4 (fp16) and max-reduce; then each thread computes one (voxel, out-col).
__global__ void __launch_bounds__(128)
k_pool_final(const float* __restrict__ wc, const float* __restrict__ bc, float* __restrict__ out)
{
    __shared__ float s_w[256][16];
    __shared__ float s_b[16];
    __shared__ float pooled[8][264];
    int t = threadIdx.x;
    long v8 = (long)blockIdx.x * 8;
    for (int i = t; i < 4096; i += 128) s_w[i >> 4][i & 15] = wc[i];
    if (t < 16) s_b[t] = bc[t];

    int lv = t >> 4, c16 = t & 15;
    long v = v8 + lv;
    int s = g_start[v], e = g_start[v + 1];
    float m[16];
    #pragma unroll
    for (int j = 0; j < 16; j++) m[j] = -3.402823466e38f;
    for (int p = s; p < e; p++) {
        int row = g_perm[p];
        const uint4* rp = (const uint4*)(g_h4 + (size_t)row * 256 + c16 * 16);
        uint4 x0 = rp[0], x1 = rp[1];
        __half2 hp[8];
        *(uint4*)hp       = x0;
        *(uint4*)(hp + 4) = x1;
        #pragma unroll
        for (int q = 0; q < 8; q++) {
            float2 f = __half22float2(hp[q]);
            m[2 * q]     = fmaxf(m[2 * q],     f.x);
            m[2 * q + 1] = fmaxf(m[2 * q + 1], f.y);
        }
    }
    if (s == e) {
        #pragma unroll
        for (int j = 0; j < 16; j++) m[j] = 0.f;    // empty voxel -> 0 (matches reference)
    }
    #pragma unroll
    for (int q = 0; q < 4; q++)
        *(float4*)&pooled[lv][c16 * 16 + q * 4] =
            make_float4(m[q * 4], m[q * 4 + 1], m[q * 4 + 2], m[q * 4 + 3]);
    __syncthreads();

    int lv2 = t >> 4, o = t & 15;
    float a = s_b[o];
    const float4* pr = (const float4*)&pooled[lv2][0];
    #pragma unroll 8
    for (int k4 = 0; k4 < 64; k4++) {
        float4 x = pr[k4];
        a = fmaf(x.x, s_w[k4 * 4 + 0][o], a);
        a = fmaf(x.y, s_w[k4 * 4 + 1][o], a);
        a = fmaf(x.z, s_w[k4 * 4 + 2][o], a);
        a = fmaf(x.w, s_w[k4 * 4 + 3][o], a);
    }
    out[(size_t)(v8 + lv2) * 16 + o] = fmaxf(a, 0.f);
}

// ===================== launch =====================
#define SMEMB(NOUT_) (10240 + 2 * (NOUT_) * 80 + 5 * 1024)

extern "C" void kernel_launch(void* const* d_in, const int* in_sizes, int n_in,
                              void* d_out, int out_size)
{
    const float* pt   = (const float*)d_in[0];
    const float* bn0g = (const float*)d_in[1];
    const float* bn0b = (const float*)d_in[2];
    const float* w1   = (const float*)d_in[3];
    const float* b1   = (const float*)d_in[4];
    const float* bn1g = (const float*)d_in[5];
    const float* bn1b = (const float*)d_in[6];
    const float* w2   = (const float*)d_in[7];
    const float* b2   = (const float*)d_in[8];
    const float* bn2g = (const float*)d_in[9];
    const float* bn2b = (const float*)d_in[10];
    const float* w3   = (const float*)d_in[11];
    const float* b3   = (const float*)d_in[12];
    const float* bn3g = (const float*)d_in[13];
    const float* bn3b = (const float*)d_in[14];
    const float* w4   = (const float*)d_in[15];
    const float* b4   = (const float*)d_in[16];
    const float* wc   = (const float*)d_in[17];
    const float* bc   = (const float*)d_in[18];
    const int*   uinv = (const int*)d_in[19];
    float* out = (float*)d_out;

    __half *h1, *h2, *h3, *h4, *w2i, *w3i, *w4i;
    cudaGetSymbolAddress((void**)&h1, g_h1);
    cudaGetSymbolAddress((void**)&h2, g_h2);
    cudaGetSymbolAddress((void**)&h3, g_h3);
    cudaGetSymbolAddress((void**)&h4, g_h4);
    cudaGetSymbolAddress((void**)&w2i, g_w2);
    cudaGetSymbolAddress((void**)&w3i, g_w3);
    cudaGetSymbolAddress((void**)&w4i, g_w4);

    cudaFuncSetAttribute(k_mma<64, 128, true>,   cudaFuncAttributeMaxDynamicSharedMemorySize, SMEMB(128));
    cudaFuncSetAttribute(k_mma<128, 256, true>,  cudaFuncAttributeMaxDynamicSharedMemorySize, SMEMB(256));
    cudaFuncSetAttribute(k_mma<256, 256, false>, cudaFuncAttributeMaxDynamicSharedMemorySize, SMEMB(256));

    const int GM = (N_PTS + 127) / 128;        // 4688 (layer 1)
    const int GB = N_PTS / 64;                 // 9375 (layers 2-4, exact)
    const int NSB = (N_VOX + SCB - 1) / SCB;   // 391 scan blocks

    k_init<<<(N_VOX + 255) / 256, 256>>>();
    k_stats_in<<<1024, 256>>>(pt);
    k_wprep<<<416, 256>>>(w2, w3, w4);
    k_hist<<<(N_PTS + 255) / 256, 256>>>(uinv);
    k_scan1<<<NSB, SCB>>>();
    k_scan2<<<1, SCB>>>(NSB);
    k_scan3<<<NSB, SCB>>>();
    k_scatter<<<(N_PTS + 255) / 256, 256>>>(uinv);
    k_prep<<<1, 256>>>(bn0g, bn0b, 0, 16);
    k_gemm<16, 64, false><<<dim3(1, GM), 256>>>(pt, w1, b1, 64, 0, 1, h1);
    k_prep<<<1, 256>>>(bn1g, bn1b, 1, 64);
    k_mma<64, 128, true><<<GB, 256, SMEMB(128)>>>(h1, w2i, b2, 1, 2, h2);
    k_prep<<<1, 256>>>(bn2g, bn2b, 2, 128);
    k_mma<128, 256, true><<<GB, 256, SMEMB(256)>>>(h2, w3i, b3, 2, 3, h3);
    k_prep<<<1, 256>>>(bn3g, bn3b, 3, 256);
    k_mma<256, 256, false><<<GB, 256, SMEMB(256)>>>(h3, w4i, b4, 3, 0, h4);
    k_pool_final<<<N_VOX / 8, 128>>>(wc, bc, out);
}